// round 3
// baseline (speedup 1.0000x reference)
#include <cuda_runtime.h>
#include <cstdint>

#define NN 65536
#define DD 64
#define EE 1048576
#define SS 1024

// Scratch (device globals — no allocation allowed)
__device__ float g_z[NN * DD];     // z = (1+eps)h + agg, later reused for gemm2 output
__device__ float g_y[NN * DD];     // gemm1 output
__device__ float g_h[NN * DD];     // layer output (next layer input)
__device__ float g_stats[256];     // [0:64) sum, [64:128) sumsq, [128:192) scale, [192:256) shift

// ---------------------------------------------------------------------------
__global__ void zero_out_kernel(float* __restrict__ out) {
    int i = blockIdx.x * blockDim.x + threadIdx.x;
    ((float4*)out)[i] = make_float4(0.f, 0.f, 0.f, 0.f);
}

// z = (1+eps[l]) * h_in ; also zero BN accumulators
__global__ void init_z_kernel(const float* __restrict__ x,
                              const float* __restrict__ eps, int layer) {
    const float* h_in = layer ? g_h : x;
    int i = blockIdx.x * 256 + threadIdx.x;
    float s = 1.0f + __ldg(eps + layer);
    float4 v = __ldg(((const float4*)h_in) + i);
    v.x *= s; v.y *= s; v.z *= s; v.w *= s;
    ((float4*)g_z)[i] = v;
    if (blockIdx.x == 0 && threadIdx.x < 128) g_stats[threadIdx.x] = 0.f;
}

// z[dst] += h[src] for every edge; 16 threads/edge, one red.v4 each
__global__ void agg_kernel(const float* __restrict__ x,
                           const int* __restrict__ ei, int layer) {
    const float* h_in = layer ? g_h : x;
    unsigned tid = blockIdx.x * 256u + threadIdx.x;
    unsigned e = tid >> 4, q = tid & 15u;
    int s = __ldg(ei + e);
    int d = __ldg(ei + EE + e);
    float4 v = __ldg((const float4*)(h_in + (size_t)s * DD) + q);
    float* p = g_z + (size_t)d * DD + q * 4;
    asm volatile("red.global.add.v4.f32 [%0], {%1,%2,%3,%4};"
                 :: "l"(p), "f"(v.x), "f"(v.y), "f"(v.z), "f"(v.w)
                 : "memory");
}

// out = in @ W + b  (optionally in := relu(in*scale+shift) on load),
// plus per-column sum / sumsq accumulation for BN.
// BN=false: g_z -> g_y ; BN=true: g_y -> g_z
template <bool BN>
__global__ void __launch_bounds__(256)
gemm_kernel(const float* __restrict__ W, const float* __restrict__ bias) {
    const float* in = BN ? g_y : g_z;
    float* out      = BN ? g_z : g_y;
    __shared__ float ws[DD * DD];
    __shared__ float zs[DD * DD];
    __shared__ float ssc[DD], ssh[DD];
    int t = threadIdx.x;

    #pragma unroll
    for (int p = 0; p < 4; p++)
        ((float4*)ws)[t + p * 256] = __ldg(((const float4*)W) + t + p * 256);
    if (BN && t < 32) {
        if (t < 16) ((float4*)ssc)[t]      = *(((const float4*)(g_stats + 128)) + t);
        else        ((float4*)ssh)[t - 16] = *(((const float4*)(g_stats + 192)) + (t - 16));
    }
    __syncthreads();

    const float4* in4 = (const float4*)(in + (size_t)blockIdx.x * DD * DD);
    #pragma unroll
    for (int p = 0; p < 4; p++) {
        int f = t + p * 256;
        float4 v = __ldg(in4 + f);
        if (BN) {
            int c = (f & 15) * 4;
            v.x = fmaxf(fmaf(v.x, ssc[c + 0], ssh[c + 0]), 0.f);
            v.y = fmaxf(fmaf(v.y, ssc[c + 1], ssh[c + 1]), 0.f);
            v.z = fmaxf(fmaf(v.z, ssc[c + 2], ssh[c + 2]), 0.f);
            v.w = fmaxf(fmaf(v.w, ssc[c + 3], ssh[c + 3]), 0.f);
        }
        ((float4*)zs)[f] = v;
    }
    __syncthreads();

    int tr = t >> 4, tc = t & 15;
    float acc[4][4];
    #pragma unroll
    for (int i = 0; i < 4; i++)
        #pragma unroll
        for (int j = 0; j < 4; j++) acc[i][j] = 0.f;

    #pragma unroll 4
    for (int k = 0; k < DD; k += 4) {
        float4 a[4], b[4];
        #pragma unroll
        for (int ri = 0; ri < 4; ri++)
            a[ri] = *(const float4*)(zs + (tr * 4 + ri) * DD + k);
        #pragma unroll
        for (int kk = 0; kk < 4; kk++)
            b[kk] = *(const float4*)(ws + (k + kk) * DD + tc * 4);
        #pragma unroll
        for (int ri = 0; ri < 4; ri++) {
            const float* av = (const float*)&a[ri];
            #pragma unroll
            for (int kk = 0; kk < 4; kk++) {
                acc[ri][0] = fmaf(av[kk], b[kk].x, acc[ri][0]);
                acc[ri][1] = fmaf(av[kk], b[kk].y, acc[ri][1]);
                acc[ri][2] = fmaf(av[kk], b[kk].z, acc[ri][2]);
                acc[ri][3] = fmaf(av[kk], b[kk].w, acc[ri][3]);
            }
        }
    }

    float4 bb = __ldg(((const float4*)bias) + tc);
    float cs[4] = {0, 0, 0, 0}, cq[4] = {0, 0, 0, 0};
    #pragma unroll
    for (int ri = 0; ri < 4; ri++) {
        float4 o;
        o.x = acc[ri][0] + bb.x; o.y = acc[ri][1] + bb.y;
        o.z = acc[ri][2] + bb.z; o.w = acc[ri][3] + bb.w;
        *(float4*)(out + ((size_t)blockIdx.x * DD + tr * 4 + ri) * DD + tc * 4) = o;
        cs[0] += o.x; cs[1] += o.y; cs[2] += o.z; cs[3] += o.w;
        cq[0] += o.x * o.x; cq[1] += o.y * o.y; cq[2] += o.z * o.z; cq[3] += o.w * o.w;
    }

    __syncthreads();  // done reading zs/ws; reuse as reduction buffers
    #pragma unroll
    for (int j = 0; j < 4; j++) {
        zs[tr * DD + tc * 4 + j] = cs[j];
        ws[tr * DD + tc * 4 + j] = cq[j];
    }
    __syncthreads();
    if (t < DD) {
        float s1 = 0.f, s2 = 0.f;
        #pragma unroll
        for (int g = 0; g < 16; g++) {
            s1 += zs[g * DD + t];
            s2 += ws[g * DD + t];
        }
        atomicAdd(&g_stats[t], s1);
        atomicAdd(&g_stats[DD + t], s2);
    }
}

// BN finalize: scale/shift from accumulated sum/sumsq; re-zero accumulators
__global__ void finalize_kernel(const float* __restrict__ gamma,
                                const float* __restrict__ beta) {
    int c = threadIdx.x;
    float mu  = g_stats[c]      * (1.0f / NN);
    float ex2 = g_stats[DD + c] * (1.0f / NN);
    float var = ex2 - mu * mu;
    float sc = __ldg(gamma + c) * rsqrtf(var + 1e-5f);
    g_stats[128 + c] = sc;
    g_stats[192 + c] = __ldg(beta + c) - mu * sc;
    g_stats[c] = 0.f;
    g_stats[DD + c] = 0.f;
}

// h = relu(z2*scale+shift); segment-max into out[:, layer*64 : layer*64+64]
__global__ void __launch_bounds__(256)
apply_kernel(const int* __restrict__ n2s, float* __restrict__ out, int layer) {
    __shared__ float red[16 * DD];
    int t = threadIdx.x, b = blockIdx.x;
    int g = t >> 4, q = t & 15;
    int c0 = q * 4;
    float s0 = g_stats[128 + c0], s1 = g_stats[128 + c0 + 1];
    float s2 = g_stats[128 + c0 + 2], s3 = g_stats[128 + c0 + 3];
    float h0 = g_stats[192 + c0], h1 = g_stats[192 + c0 + 1];
    float h2 = g_stats[192 + c0 + 2], h3 = g_stats[192 + c0 + 3];

    float4 m = make_float4(0.f, 0.f, 0.f, 0.f);
    #pragma unroll
    for (int p = 0; p < 4; p++) {
        int row = b * 64 + p * 16 + g;
        float4 v = *(const float4*)(g_z + (size_t)row * DD + c0);
        v.x = fmaxf(fmaf(v.x, s0, h0), 0.f);
        v.y = fmaxf(fmaf(v.y, s1, h1), 0.f);
        v.z = fmaxf(fmaf(v.z, s2, h2), 0.f);
        v.w = fmaxf(fmaf(v.w, s3, h3), 0.f);
        *(float4*)(g_h + (size_t)row * DD + c0) = v;
        m.x = fmaxf(m.x, v.x); m.y = fmaxf(m.y, v.y);
        m.z = fmaxf(m.z, v.z); m.w = fmaxf(m.w, v.w);
    }
    red[g * DD + c0 + 0] = m.x; red[g * DD + c0 + 1] = m.y;
    red[g * DD + c0 + 2] = m.z; red[g * DD + c0 + 3] = m.w;
    __syncthreads();

    if (t < DD) {
        float mv = red[t];
        #pragma unroll
        for (int gg = 1; gg < 16; gg++) mv = fmaxf(mv, red[gg * DD + t]);
        int sA = __ldg(n2s + b * 64), sB = __ldg(n2s + b * 64 + 63);
        if (sA == sB) {
            // whole 64-row block in one segment (the expected layout)
            unsigned* p = (unsigned*)(out + (size_t)sA * 128 + layer * 64 + t);
            asm volatile("red.global.max.u32 [%0], %1;"
                         :: "l"(p), "r"(__float_as_uint(mv)) : "memory");
        } else {
            // correctness fallback: per-row segment max
            for (int r = 0; r < 64; r++) {
                int seg = __ldg(n2s + b * 64 + r);
                float v = g_h[((size_t)b * 64 + r) * DD + t];
                unsigned* p = (unsigned*)(out + (size_t)seg * 128 + layer * 64 + t);
                asm volatile("red.global.max.u32 [%0], %1;"
                             :: "l"(p), "r"(__float_as_uint(v)) : "memory");
            }
        }
    }
}

// ---------------------------------------------------------------------------
extern "C" void kernel_launch(void* const* d_in, const int* in_sizes, int n_in,
                              void* d_out, int out_size) {
    const float* x   = (const float*)d_in[0];
    const int*   ei  = (const int*)d_in[1];
    const int*   n2s = (const int*)d_in[2];
    const float* eps = (const float*)d_in[3];
    const float* W1  = (const float*)d_in[4];
    const float* b1  = (const float*)d_in[5];
    const float* gm  = (const float*)d_in[6];
    const float* bm  = (const float*)d_in[7];
    const float* W2  = (const float*)d_in[8];
    const float* b2  = (const float*)d_in[9];
    const float* go  = (const float*)d_in[10];
    const float* bo  = (const float*)d_in[11];
    float* out = (float*)d_out;

    zero_out_kernel<<<(SS * 128 / 4) / 256, 256>>>(out);

    for (int l = 0; l < 2; l++) {
        init_z_kernel<<<(NN * DD / 4) / 256, 256>>>(x, eps, l);
        agg_kernel<<<(EE * 16) / 256, 256>>>(x, ei, l);
        gemm_kernel<false><<<NN / DD, 256>>>(W1 + l * DD * DD, b1 + l * DD);
        finalize_kernel<<<1, DD>>>(gm + l * DD, bm + l * DD);
        gemm_kernel<true><<<NN / DD, 256>>>(W2 + l * DD * DD, b2 + l * DD);
        finalize_kernel<<<1, DD>>>(go + l * DD, bo + l * DD);
        apply_kernel<<<NN / DD, 256>>>(n2s, out, l);
    }
}